// round 15
// baseline (speedup 1.0000x reference)
#include <cuda_runtime.h>
#include <stdint.h>

// IN:  x (4, 64, 224, 224) fp32
// OUT: (4, 576, 223*223) fp32, plane ck = bc*9 + ki*3 + kj
// out[ck, oh*223+ow] = x[bc, oh+ki-1, ow+kj-1] (0 if OOB)
#define OSP    49729u     // 223*223
#define ISTR   50176u     // 224*224
#define ROWB   892u       // 223 * 4 bytes

// v14 with default write-back stores instead of __stcs:
// .cs evict-first was draining boundary sectors before both 16B halves
// arrived (ECC partial-sector RMW) and reducing L2 write coalescing.
__global__ void __launch_bounds__(288, 7) unfold_v15(const float* __restrict__ x,
                                                     float* __restrict__ out) {
    __shared__ __align__(16) float sbuf[11][232];  // 4 zero | 224 data | 4 zero
    unsigned g8  = blockIdx.x * 8u;
    unsigned bc  = blockIdx.y;
    unsigned tid = threadIdx.x;
    unsigned w = tid >> 5, lane = tid & 31u;

    // zero the 8 pad floats of each of the 11 rows
    if (tid < 88u) {
        unsigned sr = tid >> 3u, p = tid & 7u;
        sbuf[sr][p < 4u ? p : 224u + p] = 0.0f;
    }
    // vector staging: 11 rows x 56 float4 across all 288 threads
    {
        const float4* xb4 = (const float4*)(x + (size_t)bc * ISTR);
        for (unsigned f = tid; f < 616u; f += 288u) {
            unsigned sr = f / 56u;
            unsigned q  = f - 56u * sr;
            int ih = (int)g8 - 1 + (int)sr;
            float4 v = make_float4(0.f, 0.f, 0.f, 0.f);
            if ((unsigned)ih < 224u) v = __ldg(xb4 + (unsigned)ih * 56u + q);
            *((float4*)&sbuf[sr][4] + q) = v;
        }
    }
    __syncthreads();

    unsigned ki = w / 3u;
    unsigned kj = w - 3u * ki;
    unsigned ck = bc * 9u + w;
    unsigned nrows = (g8 + 8u <= 223u) ? 8u : (223u - g8);   // 8, last chunk 7
    unsigned kj3 = kj + 3u;

    // 32-bit byte offsets (total out = 458MB < 4GB)
    char* outc = (char*)out;
    unsigned orow = ck * (OSP * 4u) + g8 * ROWB;   // byte offset of row g8
    unsigned lead = (4u - ((orow >> 2) & 3u)) & 3u;
    const float* srow = sbuf[ki];                   // bumped +232 per r

    for (unsigned r = 0; r < nrows; ++r) {
        unsigned off = lead + kj3;          // padded-row idx of first body float
        unsigned dlt = off & 3u;
        unsigned jb  = off >> 2u;
        const float4* sm4 = (const float4*)srow;
        float4* dst4 = (float4*)(outc + orow + 4u * lead);

        // 55 fully-in-row aligned float4 stores (default .wb policy)
        for (unsigned j = lane; j < 55u; j += 32u) {
            float4 a = sm4[jb + j];
            float4 b = sm4[jb + j + 1u];
            float4 v;
            switch (dlt) {
              case 0:  v = a; break;
              case 1:  v = make_float4(a.y, a.z, a.w, b.x); break;
              case 2:  v = make_float4(a.z, a.w, b.x, b.y); break;
              default: v = make_float4(a.w, b.x, b.y, b.z); break;
            }
            dst4[j] = v;
        }

        unsigned oh   = g8 + r;
        unsigned tail = 3u - lead;

        // straddle float4 across row boundary (tail of oh + lead of oh+1)
        if (lane == 0u && tail != 0u && oh < 222u) {
            float vv[4];
#pragma unroll
            for (unsigned t = 0; t < 4u; ++t) {
                vv[t] = (t < tail) ? srow[off + 220u + t]
                                   : srow[232u + (t - tail) + kj3];
            }
            *(float4*)(outc + orow + 4u * lead + 880u) =
                make_float4(vv[0], vv[1], vv[2], vv[3]);
        }

        // plane-end tail scalars (oh == 222 only)
        if (oh == 222u && lane < tail) {
            *(float*)(outc + orow + 4u * (lead + 220u + lane)) =
                srow[off + 220u + lane];
        }

        // plane-start head scalars (first chunk, first row only)
        if (g8 == 0u && r == 0u && lane < lead) {
            *(float*)(outc + orow + 4u * lane) = srow[lane + kj3];
        }

        orow += ROWB;
        lead = (lead + 1u) & 3u;            // 223 % 4 == 3 => lead cycles +1
        srow += 232u;
    }
}

extern "C" void kernel_launch(void* const* d_in, const int* in_sizes, int n_in,
                              void* d_out, int out_size) {
    const float* x = (const float*)d_in[0];
    float* out = (float*)d_out;
    dim3 grid(28, 256);   // 28 row-groups (27*8 + 7), 256 bc planes
    unfold_v15<<<grid, 288>>>(x, out);
}

// round 16
// speedup vs baseline: 1.0105x; 1.0105x over previous
#include <cuda_runtime.h>
#include <stdint.h>

// IN:  x (4, 64, 224, 224) fp32
// OUT: (4, 576, 223*223) fp32, plane ck = bc*9 + ki*3 + kj
// out[ck, oh*223+ow] = x[bc, oh+ki-1, ow+kj-1] (0 if OOB)
#define OSP    49729u     // 223*223
#define ISTR   50176u     // 224*224
#define ROWB   892u       // 223 * 4 bytes

// Branchless 4-way word-select of P[dlt..dlt+3] from two adjacent float4s.
// Warp-uniform dlt -> FSEL chains, no BSSY/BRA/BSYNC per row.
__device__ __forceinline__ float4 shift4(unsigned dlt, float4 a, float4 b) {
    bool ge2 = dlt >= 2u;
    bool odd = dlt & 1u;
    float r0 = ge2 ? a.z : a.x;   // base for v.x at dlt&~1
    float r1 = ge2 ? a.w : a.y;
    float r2 = ge2 ? b.x : a.z;
    float r3 = ge2 ? b.y : a.w;
    float r4 = ge2 ? b.z : b.x;
    float4 v;
    v.x = odd ? r1 : r0;
    v.y = odd ? r2 : r1;
    v.z = odd ? r3 : r2;
    v.w = odd ? r4 : r3;
    return v;
}

__global__ void __launch_bounds__(288, 7) unfold_v16(const float* __restrict__ x,
                                                     float* __restrict__ out) {
    __shared__ __align__(16) float sbuf[11][232];  // 4 zero | 224 data | 4 zero
    unsigned g8  = blockIdx.x * 8u;
    unsigned bc  = blockIdx.y;
    unsigned tid = threadIdx.x;
    unsigned w = tid >> 5, lane = tid & 31u;

    // zero the 8 pad floats of each of the 11 rows
    if (tid < 88u) {
        unsigned sr = tid >> 3u, p = tid & 7u;
        sbuf[sr][p < 4u ? p : 224u + p] = 0.0f;
    }
    // vector staging: 11 rows x 56 float4 across all 288 threads
    {
        const float4* xb4 = (const float4*)(x + (size_t)bc * ISTR);
        for (unsigned f = tid; f < 616u; f += 288u) {
            unsigned sr = f / 56u;
            unsigned q  = f - 56u * sr;
            int ih = (int)g8 - 1 + (int)sr;
            float4 v = make_float4(0.f, 0.f, 0.f, 0.f);
            if ((unsigned)ih < 224u) v = __ldg(xb4 + (unsigned)ih * 56u + q);
            *((float4*)&sbuf[sr][4] + q) = v;
        }
    }
    __syncthreads();

    unsigned ki = w / 3u;
    unsigned kj = w - 3u * ki;
    unsigned ck = bc * 9u + w;
    unsigned nrows = (g8 + 8u <= 223u) ? 8u : (223u - g8);   // 8, last chunk 7
    unsigned kj3 = kj + 3u;

    // 32-bit byte offsets (total out = 458MB < 4GB)
    char* outc = (char*)out;
    unsigned orow = ck * (OSP * 4u) + g8 * ROWB;   // byte offset of row g8
    unsigned lead = (4u - ((orow >> 2) & 3u)) & 3u;
    const float* srow = sbuf[ki];                   // bumped +232 per r

    for (unsigned r = 0; r < nrows; ++r) {
        unsigned off = lead + kj3;          // padded-row idx of first body float
        unsigned dlt = off & 3u;
        unsigned jb  = off >> 2u;
        const float4* sm4 = (const float4*)srow;
        float4* dst4 = (float4*)(outc + orow + 4u * lead);

        // 55 fully-in-row aligned float4 stores, branchless select
        {
            float4 a0 = sm4[jb + lane];
            float4 b0 = sm4[jb + lane + 1u];
            dst4[lane] = shift4(dlt, a0, b0);
            if (lane < 23u) {
                float4 a1 = sm4[jb + lane + 32u];
                float4 b1 = sm4[jb + lane + 33u];
                dst4[lane + 32u] = shift4(dlt, a1, b1);
            }
        }

        unsigned oh   = g8 + r;
        unsigned tail = 3u - lead;

        // straddle float4 across row boundary (tail of oh + lead of oh+1)
        if (lane == 0u && tail != 0u && oh < 222u) {
            float vv[4];
#pragma unroll
            for (unsigned t = 0; t < 4u; ++t) {
                vv[t] = (t < tail) ? srow[off + 220u + t]
                                   : srow[232u + (t - tail) + kj3];
            }
            *(float4*)(outc + orow + 4u * lead + 880u) =
                make_float4(vv[0], vv[1], vv[2], vv[3]);
        }

        // plane-end tail scalars (oh == 222 only)
        if (oh == 222u && lane < tail) {
            *(float*)(outc + orow + 4u * (lead + 220u + lane)) =
                srow[off + 220u + lane];
        }

        // plane-start head scalars (first chunk, first row only)
        if (g8 == 0u && r == 0u && lane < lead) {
            *(float*)(outc + orow + 4u * lane) = srow[lane + kj3];
        }

        orow += ROWB;
        lead = (lead + 1u) & 3u;            // 223 % 4 == 3 => lead cycles +1
        srow += 232u;
    }
}

extern "C" void kernel_launch(void* const* d_in, const int* in_sizes, int n_in,
                              void* d_out, int out_size) {
    const float* x = (const float*)d_in[0];
    float* out = (float*)d_out;
    dim3 grid(28, 256);   // 28 row-groups (27*8 + 7), 256 bc planes
    unfold_v16<<<grid, 288>>>(x, out);
}